// round 1
// baseline (speedup 1.0000x reference)
#include <cuda_runtime.h>
#include <math.h>

#define Bb 16
#define Nn 1024
#define Dd 512
#define Kk 8
#define NITER 3
#define NROWCHUNK 32   // row chunks per batch for colsum partials (1024/32 = 32 rows/chunk)
#define NCHUNK 8       // n-split for mu/v2 partials

__device__ __constant__ float c_EPS = 1e-8f;
__device__ __constant__ float c_LNEPS = 1e-5f;
__device__ __constant__ float c_LOG2PI = 1.8378770664093453f;

// ---------------- scratch (static device globals; allocation-free) ----------
__device__ float g_mean[Bb*Nn];
__device__ float g_rstd[Bb*Nn];
__device__ float g_keys[Bb*Nn*Dd];
__device__ float g_values[Bb*Nn*Dd];
__device__ float g_q[Bb*Kk*Dd];
__device__ float g_sigma[Bb*Kk*Dd];
__device__ float g_w[Bb*Kk*Dd];
__device__ float g_qw[Bb*Kk*Dd];
__device__ float g_c1[Bb*Kk];
__device__ float g_mixing[Bb*Kk];
__device__ float g_attn[Bb*Nn*Kk];          // attn after K-normalization (pre column-norm)
__device__ float g_Spart[Bb*NROWCHUNK*Kk];  // partial column sums
__device__ float g_S[Bb*Kk];
__device__ float g_mupart[NCHUNK*Bb*Kk*Dd];
__device__ float g_v2part[NCHUNK*Bb*Kk*Dd];
__device__ float g_mu[Bb*Kk*Dd];

// ---------------- K0: layernorm row statistics ------------------------------
__global__ void ln_stats(const float* __restrict__ E) {
    int row = blockIdx.x;                  // 0..B*N-1
    const float* x = E + (size_t)row * Dd;
    int t = threadIdx.x;                   // 128 threads
    float s = 0.f, s2 = 0.f;
    #pragma unroll
    for (int i = t; i < Dd; i += 128) { float v = x[i]; s += v; s2 += v * v; }
    #pragma unroll
    for (int o = 16; o; o >>= 1) {
        s  += __shfl_xor_sync(0xffffffffu, s,  o);
        s2 += __shfl_xor_sync(0xffffffffu, s2, o);
    }
    __shared__ float sh[2][4];
    if ((t & 31) == 0) { sh[0][t >> 5] = s; sh[1][t >> 5] = s2; }
    __syncthreads();
    if (t == 0) {
        float S  = sh[0][0] + sh[0][1] + sh[0][2] + sh[0][3];
        float S2 = sh[1][0] + sh[1][1] + sh[1][2] + sh[1][3];
        float m = S / (float)Dd;
        float var = S2 / (float)Dd - m * m;
        g_mean[row] = m;
        g_rstd[row] = rsqrtf(var + c_LNEPS);
    }
}

// ---------------- K1: fused LN + GEMM -> keys, values -----------------------
// Virtual GEMM: [16384 x 512] @ [512 x 1024] (Wk|Wv). 128x128x8 tiles, 256 thr, 8x8/thread.
__global__ __launch_bounds__(256) void gemm_kv(
    const float* __restrict__ E,
    const float* __restrict__ lng, const float* __restrict__ lnb,
    const float* __restrict__ Wk,  const float* __restrict__ Wv,
    const float* __restrict__ bk,  const float* __restrict__ bv)
{
    const int BM = 128, BN = 128, BK = 8;
    __shared__ float As[BK][BM];
    __shared__ float Bs[BK][BN];
    int bx = blockIdx.x;                       // 0..7 (cols 0..3 -> Wk, 4..7 -> Wv)
    int by = blockIdx.y;                       // 0..127
    int tid = threadIdx.x;
    const float* Bsrc = (bx < 4) ? Wk : Wv;
    const float* bias = (bx < 4) ? bk : bv;
    float* Dst        = (bx < 4) ? g_keys : g_values;
    int cb = (bx & 3) * BN;
    int m0 = by * BM;

    int arow = tid >> 1;           // 0..127
    int acol = (tid & 1) * 4;      // 0 or 4
    int brow = tid >> 5;           // 0..7
    int bcol = (tid & 31) * 4;     // 0..124
    int gr = m0 + arow;
    float mu = g_mean[gr], rs = g_rstd[gr];

    int ty = (tid >> 4) * 8;       // 0..120
    int tx = (tid & 15) * 8;       // 0..120

    float acc[8][8];
    #pragma unroll
    for (int i = 0; i < 8; i++)
        #pragma unroll
        for (int j = 0; j < 8; j++) acc[i][j] = 0.f;

    for (int k0 = 0; k0 < Dd; k0 += BK) {
        float4 a  = *(const float4*)(E + (size_t)gr * Dd + k0 + acol);
        float4 g4 = *(const float4*)(lng + k0 + acol);
        float4 b4 = *(const float4*)(lnb + k0 + acol);
        As[acol + 0][arow] = (a.x - mu) * rs * g4.x + b4.x;
        As[acol + 1][arow] = (a.y - mu) * rs * g4.y + b4.y;
        As[acol + 2][arow] = (a.z - mu) * rs * g4.z + b4.z;
        As[acol + 3][arow] = (a.w - mu) * rs * g4.w + b4.w;
        *(float4*)&Bs[brow][bcol] = *(const float4*)(Bsrc + (size_t)(k0 + brow) * Dd + cb + bcol);
        __syncthreads();
        #pragma unroll
        for (int kk = 0; kk < BK; kk++) {
            float ra[8], rb[8];
            *(float4*)&ra[0] = *(float4*)&As[kk][ty];
            *(float4*)&ra[4] = *(float4*)&As[kk][ty + 4];
            *(float4*)&rb[0] = *(float4*)&Bs[kk][tx];
            *(float4*)&rb[4] = *(float4*)&Bs[kk][tx + 4];
            #pragma unroll
            for (int i = 0; i < 8; i++)
                #pragma unroll
                for (int j = 0; j < 8; j++) acc[i][j] += ra[i] * rb[j];
        }
        __syncthreads();
    }
    #pragma unroll
    for (int i = 0; i < 8; i++) {
        float* drow = Dst + (size_t)(m0 + ty + i) * Dd + cb + tx;
        #pragma unroll
        for (int j = 0; j < 8; j++) drow[j] = acc[i][j] + bias[cb + tx + j];
    }
}

// ---------------- K2: sample slots, queries = slots@Wq + bq, init sigma/mix -
__global__ void init_slots_queries(
    const float* __restrict__ noise_init, const float* __restrict__ slots_mu,
    const float* __restrict__ slots_ls,   const float* __restrict__ mix_in,
    const float* __restrict__ Wq,         const float* __restrict__ bq)
{
    int bk_ = blockIdx.x;                 // 0..127
    int b = bk_ >> 3, k = bk_ & 7;
    __shared__ float slot[Dd];
    int t = threadIdx.x;                  // 128
    for (int d = t; d < Dd; d += 128) {
        float sg = expf(slots_ls[k * Dd + d]);
        slot[d] = slots_mu[k * Dd + d] + sg * noise_init[((size_t)b * Kk + k) * Dd + d];
        g_sigma[((size_t)b * Kk + k) * Dd + d] = sg;
    }
    if (t == 0) g_mixing[b * Kk + k] = mix_in[k];
    __syncthreads();
    for (int j = t; j < Dd; j += 128) {
        float acc = bq[j];
        for (int d = 0; d < Dd; d++) acc += slot[d] * Wq[(size_t)d * Dd + j];
        g_q[((size_t)b * Kk + k) * Dd + j] = acc;
    }
}

// ---------------- K3: per-(b,k) precompute w, qw, c1 ------------------------
__global__ void prep_iter() {
    int bk_ = blockIdx.x;                  // 0..127
    int t = threadIdx.x;                   // 128
    float slog = 0.f, sqwq = 0.f;
    for (int d = t; d < Dd; d += 128) {
        float sg = g_sigma[(size_t)bk_ * Dd + d];
        float w  = 1.f / (sg * sg + c_EPS);
        float q  = g_q[(size_t)bk_ * Dd + d];
        g_w [(size_t)bk_ * Dd + d] = w;
        g_qw[(size_t)bk_ * Dd + d] = q * w;
        slog += logf(fabsf(sg) + c_EPS);
        sqwq += q * q * w;
    }
    #pragma unroll
    for (int o = 16; o; o >>= 1) {
        slog += __shfl_xor_sync(0xffffffffu, slog, o);
        sqwq += __shfl_xor_sync(0xffffffffu, sqwq, o);
    }
    __shared__ float sh[2][4];
    if ((t & 31) == 0) { sh[0][t >> 5] = slog; sh[1][t >> 5] = sqwq; }
    __syncthreads();
    if (t == 0) {
        float SL = sh[0][0] + sh[0][1] + sh[0][2] + sh[0][3];
        float SQ = sh[1][0] + sh[1][1] + sh[1][2] + sh[1][3];
        g_c1[bk_] = -0.5f * (float)Dd * c_LOG2PI - 0.5f * SL - 0.5f * SQ;
    }
}

// ---------------- K4: gll + K-normalized attn + colsum partials -------------
// grid (B, NROWCHUNK), 256 thr = 8 warps, 4 rows/warp.
__global__ __launch_bounds__(256) void gll_attn() {
    int b = blockIdx.x, chunk = blockIdx.y;
    int t = threadIdx.x, warp = t >> 5, lane = t & 31;
    __shared__ float sw[Kk * Dd];    // 16KB
    __shared__ float sqw[Kk * Dd];   // 16KB
    __shared__ float c1s[Kk], mixs[Kk];
    __shared__ float wcs[8][Kk];
    for (int i = t; i < Kk * Dd; i += 256) {
        sw [i] = g_w [(size_t)b * Kk * Dd + i];
        sqw[i] = g_qw[(size_t)b * Kk * Dd + i];
    }
    if (t < Kk) { c1s[t] = g_c1[b * Kk + t]; mixs[t] = g_mixing[b * Kk + t]; }
    __syncthreads();

    float cs = 0.f;  // per-(warp,lane<8) column partial sum
    int rbase = chunk * 32 + warp * 4;
    for (int rr = 0; rr < 4; rr++) {
        int r = rbase + rr;
        const float* krow = g_keys + ((size_t)b * Nn + r) * Dd;
        float kk[Kk], kq[Kk];
        #pragma unroll
        for (int k = 0; k < Kk; k++) { kk[k] = 0.f; kq[k] = 0.f; }
        #pragma unroll
        for (int i = 0; i < 16; i++) {
            int d = lane + 32 * i;
            float kv = krow[d];
            float kv2 = kv * kv;
            #pragma unroll
            for (int k = 0; k < Kk; k++) {
                kk[k] += kv2 * sw [k * Dd + d];
                kq[k] += kv  * sqw[k * Dd + d];
            }
        }
        #pragma unroll
        for (int o = 16; o; o >>= 1)
            #pragma unroll
            for (int k = 0; k < Kk; k++) {
                kk[k] += __shfl_xor_sync(0xffffffffu, kk[k], o);
                kq[k] += __shfl_xor_sync(0xffffffffu, kq[k], o);
            }
        float au[Kk], rsum = 0.f;
        #pragma unroll
        for (int k = 0; k < Kk; k++) {
            float gll = c1s[k] - 0.5f * kk[k] + kq[k];
            au[k] = mixs[k] * gll;
            rsum += au[k];
        }
        float inv = 1.f / rsum;
        if (lane < Kk) {
            float a = au[lane] * inv;
            g_attn[((size_t)b * Nn + r) * Kk + lane] = a;
            cs += a;
        }
    }
    if (lane < Kk) wcs[warp][lane] = cs;
    __syncthreads();
    if (t < Kk) {
        float S = 0.f;
        #pragma unroll
        for (int w = 0; w < 8; w++) S += wcs[w][t];   // fixed order: deterministic
        g_Spart[((size_t)b * NROWCHUNK + chunk) * Kk + t] = S;
    }
}

// ---------------- K6: mu / E[v^2] partials ----------------------------------
// grid (B, 4 dtiles, NCHUNK), 128 thr; thread owns one d, loops 128 n's.
__global__ __launch_bounds__(128) void mu_partial() {
    int b = blockIdx.x, dt = blockIdx.y, nc = blockIdx.z, t = threadIdx.x;
    int d = dt * 128 + t;
    int n0 = nc * 128;
    __shared__ float att[128][Kk];
    {
        const float4* src = (const float4*)(g_attn + ((size_t)b * Nn + n0 + t) * Kk);
        float4 a0 = src[0], a1 = src[1];
        att[t][0] = a0.x; att[t][1] = a0.y; att[t][2] = a0.z; att[t][3] = a0.w;
        att[t][4] = a1.x; att[t][5] = a1.y; att[t][6] = a1.z; att[t][7] = a1.w;
    }
    __syncthreads();
    float mu_[Kk], v2_[Kk];
    #pragma unroll
    for (int k = 0; k < Kk; k++) { mu_[k] = 0.f; v2_[k] = 0.f; }
    for (int i = 0; i < 128; i++) {
        float v = g_values[((size_t)b * Nn + n0 + i) * Dd + d];
        float vv = v * v;
        #pragma unroll
        for (int k = 0; k < Kk; k++) {
            float a = att[i][k];
            mu_[k] += a * v;
            v2_[k] += a * vv;
        }
    }
    #pragma unroll
    for (int k = 0; k < Kk; k++) {
        size_t idx = (((size_t)nc * Bb + b) * Kk + k) * Dd + d;
        g_mupart[idx] = mu_[k];
        g_v2part[idx] = v2_[k];
    }
}

// ---------------- K7: reduce partials; update mu, sigma, mixing -------------
__global__ void reduce_update() {
    int bk_ = blockIdx.x;                  // 0..127
    int b = bk_ >> 3, k = bk_ & 7;
    int t = threadIdx.x;                   // 128
    float S = 0.f;
    #pragma unroll
    for (int c = 0; c < NROWCHUNK; c++)
        S += g_Spart[((size_t)b * NROWCHUNK + c) * Kk + k];  // fixed order
    float denom = S + c_EPS;
    float s = S / denom;
    for (int d = t; d < Dd; d += 128) {
        float m = 0.f, v2 = 0.f;
        #pragma unroll
        for (int c = 0; c < NCHUNK; c++) {
            size_t idx = (((size_t)c * Bb + b) * Kk + k) * Dd + d;
            m  += g_mupart[idx];
            v2 += g_v2part[idx];
        }
        m  /= denom;
        v2 /= denom;
        g_mu[(size_t)bk_ * Dd + d] = m;
        g_sigma[(size_t)bk_ * Dd + d] = v2 - m * m * (2.f - s);
    }
    if (t == 0) {
        g_mixing[bk_] = s / (float)Nn;
        g_S[bk_] = S;
    }
}

// ---------------- K8: final slots out ---------------------------------------
__global__ void final_slots(const float* __restrict__ noise_final, float* __restrict__ out) {
    int idx = blockIdx.x * 256 + threadIdx.x;   // B*K*D = 65536
    float sg = fabsf(g_sigma[idx]);
    sg = fmaxf(sg, c_EPS);
    out[idx] = g_mu[idx] + sg * noise_final[idx];
}

// ---------------- K9: transposed attn out -----------------------------------
__global__ void attn_out(float* __restrict__ out) {
    int idx = blockIdx.x * 256 + threadIdx.x;   // B*K*N = 131072
    int n = idx & (Nn - 1);
    int k = (idx >> 10) & (Kk - 1);
    int b = idx >> 13;
    float denom = g_S[b * Kk + k] + c_EPS;
    out[idx] = g_attn[((size_t)b * Nn + n) * Kk + k] / denom;
}

// ---------------- launcher ---------------------------------------------------
extern "C" void kernel_launch(void* const* d_in, const int* in_sizes, int n_in,
                              void* d_out, int out_size) {
    const float* embeddings = (const float*)d_in[0];
    const float* noise_init = (const float*)d_in[1];
    const float* noise_final= (const float*)d_in[2];
    const float* slots_mu   = (const float*)d_in[3];
    const float* slots_ls   = (const float*)d_in[4];
    const float* mixing     = (const float*)d_in[5];
    const float* Wk = (const float*)d_in[6];
    const float* bk = (const float*)d_in[7];
    const float* Wq = (const float*)d_in[8];
    const float* bq = (const float*)d_in[9];
    const float* Wv = (const float*)d_in[10];
    const float* bv = (const float*)d_in[11];
    const float* lng = (const float*)d_in[12];
    const float* lnb = (const float*)d_in[13];
    float* out = (float*)d_out;

    ln_stats<<<Bb * Nn, 128>>>(embeddings);
    gemm_kv<<<dim3(8, 128), 256>>>(embeddings, lng, lnb, Wk, Wv, bk, bv);
    init_slots_queries<<<Bb * Kk, 128>>>(noise_init, slots_mu, slots_ls, mixing, Wq, bq);

    for (int it = 0; it < NITER; it++) {
        prep_iter<<<Bb * Kk, 128>>>();
        gll_attn<<<dim3(Bb, NROWCHUNK), 256>>>();
        mu_partial<<<dim3(Bb, 4, NCHUNK), 128>>>();
        reduce_update<<<Bb * Kk, 128>>>();
    }

    final_slots<<<(Bb * Kk * Dd) / 256, 256>>>(noise_final, out);
    attn_out<<<(Bb * Kk * Nn) / 256, 256>>>(out + Bb * Kk * Dd);
}

// round 8
// speedup vs baseline: 1.6754x; 1.6754x over previous
#include <cuda_runtime.h>
#include <cuda_bf16.h>
#include <cstdint>
#include <stdint.h>
#include <math.h>

#define Bb 16
#define Nn 1024
#define Dd 512
#define Kk 8
#define NITER 3
#define NROWCHUNK 32
#define NCHUNK 8

#define Mtot (Bb*Nn)     // 16384
#define Ntot (2*Dd)      // 1024 (keys cols | values cols)
#define LDA 40           // smem row stride (bf16 elems): 32 + 8 pad -> conflict-free ldmatrix

__device__ __constant__ float c_EPS = 1e-8f;
__device__ __constant__ float c_LNEPS = 1e-5f;
__device__ __constant__ float c_LOG2PI = 1.8378770664093453f;

// ---------------- scratch ----------------------------------------------------
__device__ float g_keys[Mtot*Dd];
__device__ float g_values[Mtot*Dd];
__device__ float g_q[Bb*Kk*Dd];
__device__ float g_sigma[Bb*Kk*Dd];
__device__ float g_w[Bb*Kk*Dd];
__device__ float g_qw[Bb*Kk*Dd];
__device__ float g_c1[Bb*Kk];
__device__ float g_mixing[Bb*Kk];
__device__ float g_attn[Bb*Nn*Kk];
__device__ float g_Spart[Bb*NROWCHUNK*Kk];
__device__ float g_S[Bb*Kk];
__device__ float g_mupart[NCHUNK*Bb*Kk*Dd];
__device__ float g_v2part[NCHUNK*Bb*Kk*Dd];
__device__ float g_mu[Bb*Kk*Dd];

// bf16 split operands for HMMA GEMM
__device__ __align__(16) __nv_bfloat16 g_Ahi[Mtot*Dd];
__device__ __align__(16) __nv_bfloat16 g_Alo[Mtot*Dd];
__device__ __align__(16) __nv_bfloat16 g_Bhi[Ntot*Dd];   // W^T rows: [n][k]
__device__ __align__(16) __nv_bfloat16 g_Blo[Ntot*Dd];

// ---------------- PTX helpers (baseline PTX only: sm_80-class) ---------------
__device__ __forceinline__ uint32_t smem_u32(const void* p) {
    uint32_t a;
    asm("{ .reg .u64 t; cvta.to.shared.u64 t, %1; cvt.u32.u64 %0, t; }" : "=r"(a) : "l"(p));
    return a;
}
__device__ __forceinline__ void cpasync16(uint32_t saddr, const void* g) {
    asm volatile("cp.async.ca.shared.global [%0], [%1], 16;" :: "r"(saddr), "l"(g));
}
__device__ __forceinline__ void ldm4(uint32_t* r, uint32_t addr) {
    asm volatile("ldmatrix.sync.aligned.m8n8.x4.shared.b16 {%0,%1,%2,%3}, [%4];"
        : "=r"(r[0]), "=r"(r[1]), "=r"(r[2]), "=r"(r[3]) : "r"(addr));
}
__device__ __forceinline__ void mma16816(float* c, const uint32_t* a, const uint32_t* b) {
    asm volatile(
        "mma.sync.aligned.m16n8k16.row.col.f32.bf16.bf16.f32 "
        "{%0,%1,%2,%3}, {%4,%5,%6,%7}, {%8,%9}, {%0,%1,%2,%3};"
        : "+f"(c[0]), "+f"(c[1]), "+f"(c[2]), "+f"(c[3])
        : "r"(a[0]), "r"(a[1]), "r"(a[2]), "r"(a[3]), "r"(b[0]), "r"(b[1]));
}

// pass operand selection: 0: Ahi*Bhi, 1: Ahi*Blo, 2: Alo*Bhi   (chunk = pass*16 + kc)
__device__ __forceinline__ void chunkAB(int chunk, const __nv_bfloat16*& Ap, const __nv_bfloat16*& Bp) {
    int pass = chunk >> 4;
    Ap = (pass == 2) ? g_Alo : g_Ahi;
    Bp = (pass == 1) ? g_Blo : g_Bhi;
}

// ---------------- K0: fused LN stats + bf16 hi/lo split of LN(x) -------------
__global__ __launch_bounds__(128) void ln_split(
    const float* __restrict__ E, const float* __restrict__ lng, const float* __restrict__ lnb)
{
    int row = blockIdx.x;
    int t = threadIdx.x;                   // 128
    float4 v = ((const float4*)(E + (size_t)row * Dd))[t];
    float s = v.x + v.y + v.z + v.w;
    float s2 = v.x*v.x + v.y*v.y + v.z*v.z + v.w*v.w;
    #pragma unroll
    for (int o = 16; o; o >>= 1) {
        s  += __shfl_xor_sync(0xffffffffu, s,  o);
        s2 += __shfl_xor_sync(0xffffffffu, s2, o);
    }
    __shared__ float sh[2][4];
    if ((t & 31) == 0) { sh[0][t >> 5] = s; sh[1][t >> 5] = s2; }
    __syncthreads();
    float S  = sh[0][0] + sh[0][1] + sh[0][2] + sh[0][3];
    float S2 = sh[1][0] + sh[1][1] + sh[1][2] + sh[1][3];
    float m = S / (float)Dd;
    float var = S2 / (float)Dd - m * m;
    float rs = rsqrtf(var + c_LNEPS);

    float4 g4 = ((const float4*)lng)[t];
    float4 b4 = ((const float4*)lnb)[t];
    float y[4];
    y[0] = (v.x - m) * rs * g4.x + b4.x;
    y[1] = (v.y - m) * rs * g4.y + b4.y;
    y[2] = (v.z - m) * rs * g4.z + b4.z;
    y[3] = (v.w - m) * rs * g4.w + b4.w;
    __nv_bfloat16 hi[4], lo[4];
    #pragma unroll
    for (int i = 0; i < 4; i++) {
        hi[i] = __float2bfloat16(y[i]);
        lo[i] = __float2bfloat16(y[i] - __bfloat162float(hi[i]));
    }
    *(uint2*)(g_Ahi + (size_t)row * Dd + t * 4) = *(uint2*)hi;
    *(uint2*)(g_Alo + (size_t)row * Dd + t * 4) = *(uint2*)lo;
}

// ---------------- K1: W^T bf16 hi/lo split (Bt[n][k] = W[k][n]) --------------
__global__ void wt_split(const float* __restrict__ Wk, const float* __restrict__ Wv) {
    __shared__ float tile[32][33];
    int n0 = blockIdx.x * 32;              // 0..1023
    int k0 = blockIdx.y * 32;              // 0..511
    const float* W = (n0 < Dd) ? Wk : Wv;
    int nc0 = n0 & (Dd - 1);
    int tx = threadIdx.x, ty = threadIdx.y;
    #pragma unroll
    for (int i = ty; i < 32; i += 8)
        tile[i][tx] = W[(size_t)(k0 + i) * Dd + nc0 + tx];   // tile[k][n]
    __syncthreads();
    #pragma unroll
    for (int i = ty; i < 32; i += 8) {
        float x = tile[tx][i];                               // W[k0+tx][n0+i]
        __nv_bfloat16 hi = __float2bfloat16(x);
        __nv_bfloat16 lo = __float2bfloat16(x - __bfloat162float(hi));
        g_Bhi[(size_t)(n0 + i) * Dd + k0 + tx] = hi;
        g_Blo[(size_t)(n0 + i) * Dd + k0 + tx] = lo;
    }
}

// ---------------- K2: HMMA bf16x3 GEMM -> keys|values ------------------------
// C[16384,1024] = A[M,512] @ Bt[N,512]^T via 3 bf16 passes (hi*hi, hi*lo, lo*hi).
// CTA tile 128x128, 8 warps (4m x 2n), warp tile 32x64, k-chunk 32, cp.async 2-stage.
__global__ __launch_bounds__(256, 2) void mma_kv(
    const float* __restrict__ bk, const float* __restrict__ bv)
{
    __shared__ __nv_bfloat16 sA[2][128 * LDA];
    __shared__ __nv_bfloat16 sB[2][128 * LDA];
    int tid = threadIdx.x, lane = tid & 31, wid = tid >> 5;
    int warp_m = wid >> 1, warp_n = wid & 1;
    int n0 = blockIdx.x * 128;
    int m0 = blockIdx.y * 128;

    float acc[2][8][4];
    #pragma unroll
    for (int i = 0; i < 2; i++)
        #pragma unroll
        for (int j = 0; j < 8; j++)
            #pragma unroll
            for (int q = 0; q < 4; q++) acc[i][j][q] = 0.f;

    const int ldrow = tid >> 2, ldseg = tid & 3;         // A/B gmem->smem mapping
    const int ldrow2 = (tid + 256) >> 2, ldseg2 = (tid + 256) & 3;

    {   // prefetch chunk 0
        const __nv_bfloat16 *Ap, *Bp; chunkAB(0, Ap, Bp);
        cpasync16(smem_u32(&sA[0][ldrow * LDA + ldseg * 8]),  Ap + (size_t)(m0 + ldrow) * Dd + ldseg * 8);
        cpasync16(smem_u32(&sA[0][ldrow2 * LDA + ldseg2 * 8]), Ap + (size_t)(m0 + ldrow2) * Dd + ldseg2 * 8);
        cpasync16(smem_u32(&sB[0][ldrow * LDA + ldseg * 8]),  Bp + (size_t)(n0 + ldrow) * Dd + ldseg * 8);
        cpasync16(smem_u32(&sB[0][ldrow2 * LDA + ldseg2 * 8]), Bp + (size_t)(n0 + ldrow2) * Dd + ldseg2 * 8);
        asm volatile("cp.async.commit_group;" ::: "memory");
    }

    for (int chunk = 0; chunk < 48; chunk++) {
        int buf = chunk & 1;
        if (chunk < 47) {
            int nc = chunk + 1;
            int kc = nc & 15;
            const __nv_bfloat16 *Ap, *Bp; chunkAB(nc, Ap, Bp);
            int nb = buf ^ 1;
            cpasync16(smem_u32(&sA[nb][ldrow * LDA + ldseg * 8]),  Ap + (size_t)(m0 + ldrow) * Dd + kc * 32 + ldseg * 8);
            cpasync16(smem_u32(&sA[nb][ldrow2 * LDA + ldseg2 * 8]), Ap + (size_t)(m0 + ldrow2) * Dd + kc * 32 + ldseg2 * 8);
            cpasync16(smem_u32(&sB[nb][ldrow * LDA + ldseg * 8]),  Bp + (size_t)(n0 + ldrow) * Dd + kc * 32 + ldseg * 8);
            cpasync16(smem_u32(&sB[nb][ldrow2 * LDA + ldseg2 * 8]), Bp + (size_t)(n0 + ldrow2) * Dd + kc * 32 + ldseg2 * 8);
            asm volatile("cp.async.commit_group;" ::: "memory");
            asm volatile("cp.async.wait_group 1;" ::: "memory");
        } else {
            asm volatile("cp.async.wait_group 0;" ::: "memory");
        }
        __syncthreads();

        #pragma unroll
        for (int ks = 0; ks < 2; ks++) {
            uint32_t a[2][4], b[8][2];
            #pragma unroll
            for (int mi = 0; mi < 2; mi++) {
                int row = warp_m * 32 + mi * 16 + (lane & 15);
                int col = ks * 16 + (lane >> 4) * 8;
                ldm4(a[mi], smem_u32(&sA[buf][row * LDA + col]));
            }
            #pragma unroll
            for (int jj = 0; jj < 4; jj++) {
                int nrow = warp_n * 64 + jj * 16 + (lane & 7) + ((lane >> 4) << 3);
                int col = ks * 16 + ((lane >> 3) & 1) * 8;
                uint32_t r4[4];
                ldm4(r4, smem_u32(&sB[buf][nrow * LDA + col]));
                b[2*jj][0] = r4[0]; b[2*jj][1] = r4[1];
                b[2*jj+1][0] = r4[2]; b[2*jj+1][1] = r4[3];
            }
            #pragma unroll
            for (int mi = 0; mi < 2; mi++)
                #pragma unroll
                for (int nj = 0; nj < 8; nj++)
                    mma16816(acc[mi][nj], a[mi], b[nj]);
        }
        __syncthreads();
    }

    // epilogue: add bias, store fp32
    const bool isK = (n0 < Dd);
    float* Dst = isK ? g_keys : g_values;
    const float* bias = isK ? bk : bv;
    int nbase = (isK ? n0 : n0 - Dd) + warp_n * 64;
    int mbase = m0 + warp_m * 32;
    int r = lane >> 2, cp = 2 * (lane & 3);
    #pragma unroll
    for (int mi = 0; mi < 2; mi++) {
        #pragma unroll
        for (int nj = 0; nj < 8; nj++) {
            int n = nbase + nj * 8 + cp;
            float b0 = bias[n], b1 = bias[n + 1];
            int m = mbase + mi * 16 + r;
            float2 o0 = { acc[mi][nj][0] + b0, acc[mi][nj][1] + b1 };
            float2 o1 = { acc[mi][nj][2] + b0, acc[mi][nj][3] + b1 };
            *(float2*)&Dst[(size_t)m * Dd + n] = o0;
            *(float2*)&Dst[(size_t)(m + 8) * Dd + n] = o1;
        }
    }
}

// ---------------- K3: sample slots, queries = slots@Wq + bq ------------------
__global__ void init_slots_queries(
    const float* __restrict__ noise_init, const float* __restrict__ slots_mu,
    const float* __restrict__ slots_ls,   const float* __restrict__ mix_in,
    const float* __restrict__ Wq,         const float* __restrict__ bq)
{
    int bk_ = blockIdx.x;                 // 0..127
    int b = bk_ >> 3, k = bk_ & 7;
    __shared__ float slot[Dd];
    int t = threadIdx.x;                  // 128
    for (int d = t; d < Dd; d += 128) {
        float sg = expf(slots_ls[k * Dd + d]);
        slot[d] = slots_mu[k * Dd + d] + sg * noise_init[((size_t)b * Kk + k) * Dd + d];
        g_sigma[((size_t)b * Kk + k) * Dd + d] = sg;
    }
    if (t == 0) g_mixing[b * Kk + k] = mix_in[k];
    __syncthreads();
    for (int j = t; j < Dd; j += 128) {
        float acc = bq[j];
        for (int d = 0; d < Dd; d++) acc += slot[d] * Wq[(size_t)d * Dd + j];
        g_q[((size_t)b * Kk + k) * Dd + j] = acc;
    }
}

// ---------------- K4: per-(b,k) precompute w, qw, c1 -------------------------
__global__ void prep_iter() {
    int bk_ = blockIdx.x;
    int t = threadIdx.x;
    float slog = 0.f, sqwq = 0.f;
    for (int d = t; d < Dd; d += 128) {
        float sg = g_sigma[(size_t)bk_ * Dd + d];
        float w  = 1.f / (sg * sg + c_EPS);
        float q  = g_q[(size_t)bk_ * Dd + d];
        g_w [(size_t)bk_ * Dd + d] = w;
        g_qw[(size_t)bk_ * Dd + d] = q * w;
        slog += logf(fabsf(sg) + c_EPS);
        sqwq += q * q * w;
    }
    #pragma unroll
    for (int o = 16; o; o >>= 1) {
        slog += __shfl_xor_sync(0xffffffffu, slog, o);
        sqwq += __shfl_xor_sync(0xffffffffu, sqwq, o);
    }
    __shared__ float sh[2][4];
    if ((t & 31) == 0) { sh[0][t >> 5] = slog; sh[1][t >> 5] = sqwq; }
    __syncthreads();
    if (t == 0) {
        float SL = sh[0][0] + sh[0][1] + sh[0][2] + sh[0][3];
        float SQ = sh[1][0] + sh[1][1] + sh[1][2] + sh[1][3];
        g_c1[bk_] = -0.5f * (float)Dd * c_LOG2PI - 0.5f * SL - 0.5f * SQ;
    }
}

// ---------------- K5: gll + K-normalized attn + colsum partials --------------
__global__ __launch_bounds__(256) void gll_attn() {
    int b = blockIdx.x, chunk = blockIdx.y;
    int t = threadIdx.x, warp = t >> 5, lane = t & 31;
    __shared__ float sw[Kk * Dd];
    __shared__ float sqw[Kk * Dd];
    __shared__ float c1s[Kk], mixs[Kk];
    __shared__ float wcs[8][Kk];
    for (int i = t; i < Kk * Dd; i += 256) {
        sw [i] = g_w [(size_t)b * Kk * Dd + i];
        sqw[i] = g_qw[(size_t)b * Kk * Dd + i];
    }
    if (t < Kk) { c1s[t] = g_c1[b * Kk + t]; mixs[t] = g_mixing[b * Kk + t]; }
    __syncthreads();

    float cs = 0.f;
    int rbase = chunk * 32 + warp * 4;
    for (int rr = 0; rr < 4; rr++) {
        int r = rbase + rr;
        const float* krow = g_keys + ((size_t)b * Nn + r) * Dd;
        float kk[Kk], kq[Kk];
        #pragma unroll
        for (int k = 0; k < Kk; k++) { kk[k] = 0.f; kq[k] = 0.f; }
        #pragma unroll
        for (int i = 0; i < 16; i++) {
            int d = lane + 32 * i;
            float kv = krow[d];
            float kv2 = kv * kv;
            #pragma unroll
            for (int k = 0; k < Kk; k++) {
                kk[k] += kv2 * sw [k * Dd + d];
                kq[k] += kv  * sqw[k * Dd + d];
            }
        }
        #pragma unroll
        for (int o = 16; o; o >>= 1)
            #pragma unroll
            for (int k = 0; k < Kk; k++) {
                kk[k] += __shfl_xor_sync(0xffffffffu, kk[k], o);
                kq[k] += __shfl_xor_sync(0xffffffffu, kq[k], o);
            }
        float au[Kk], rsum = 0.f;
        #pragma unroll
        for (int k = 0; k < Kk; k++) {
            float gll = c1s[k] - 0.5f * kk[k] + kq[k];
            au[k] = mixs[k] * gll;
            rsum += au[k];
        }
        float inv = 1.f / rsum;
        if (lane < Kk) {
            float a = au[lane] * inv;
            g_attn[((size_t)b * Nn + r) * Kk + lane] = a;
            cs += a;
        }
    }
    if (lane < Kk) wcs[warp][lane] = cs;
    __syncthreads();
    if (t < Kk) {
        float S = 0.f;
        #pragma unroll
        for (int w = 0; w < 8; w++) S += wcs[w][t];
        g_Spart[((size_t)b * NROWCHUNK + chunk) * Kk + t] = S;
    }
}

// ---------------- K6: mu / E[v^2] partials -----------------------------------
__global__ __launch_bounds__(128) void mu_partial() {
    int b = blockIdx.x, dt = blockIdx.y, nc = blockIdx.z, t = threadIdx.x;
    int d = dt * 128 + t;
    int n0 = nc * 128;
    __shared__ float att[128][Kk];
    {
        const float4* src = (const float4*)(g_attn + ((size_t)b * Nn + n0 + t) * Kk);
        float4 a0 = src[0], a1 = src[1];
        att[t][0] = a0.x; att[t][1] = a0.y; att[t][2] = a0.z; att[t][3] = a0.w;
        att[t][4] = a1.x; att[t][5] = a1.y; att[t][6] = a1.z; att[t][7] = a1.w;
    }
    __syncthreads();
    float mu_[Kk], v2_[Kk];
    #pragma unroll
    for (int k = 0; k < Kk; k++) { mu_[k] = 0.f; v2_[k] = 0.f; }
    for (int i = 0; i < 128; i++) {
        float v = g_values[((size_t)b * Nn + n0 + i) * Dd + d];
        float vv = v * v;
        #pragma unroll
        for (int k = 0; k < Kk; k++) {
            float a = att[i][k];
            mu_[k] += a * v;
            v2_[k] += a * vv;
        }
    }
    #pragma unroll
    for (int k = 0; k < Kk; k++) {
        size_t idx = (((size_t)nc * Bb + b) * Kk + k) * Dd + d;
        g_mupart[idx] = mu_[k];
        g_v2part[idx] = v2_[k];
    }
}

// ---------------- K7: reduce partials; update mu, sigma, mixing --------------
__global__ void reduce_update() {
    int bk_ = blockIdx.x;
    int b = bk_ >> 3, k = bk_ & 7;
    int t = threadIdx.x;
    float S = 0.f;
    #pragma unroll
    for (int c = 0; c < NROWCHUNK; c++)
        S += g_Spart[((size_t)b * NROWCHUNK + c) * Kk + k];
    float denom = S + c_EPS;
    float s = S / denom;
    for (int d = t; d < Dd; d += 128) {
        float m = 0.f, v2 = 0.f;
        #pragma unroll
        for (int c = 0; c < NCHUNK; c++) {
            size_t idx = (((size_t)c * Bb + b) * Kk + k) * Dd + d;
            m  += g_mupart[idx];
            v2 += g_v2part[idx];
        }
        m  /= denom;
        v2 /= denom;
        g_mu[(size_t)bk_ * Dd + d] = m;
        g_sigma[(size_t)bk_ * Dd + d] = v2 - m * m * (2.f - s);
    }
    if (t == 0) {
        g_mixing[bk_] = s / (float)Nn;
        g_S[bk_] = S;
    }
}

// ---------------- K8: final slots out ----------------------------------------
__global__ void final_slots(const float* __restrict__ noise_final, float* __restrict__ out) {
    int idx = blockIdx.x * 256 + threadIdx.x;
    float sg = fabsf(g_sigma[idx]);
    sg = fmaxf(sg, c_EPS);
    out[idx] = g_mu[idx] + sg * noise_final[idx];
}

// ---------------- K9: transposed attn out ------------------------------------
__global__ void attn_out(float* __restrict__ out) {
    int idx = blockIdx.x * 256 + threadIdx.x;
    int n = idx & (Nn - 1);
    int k = (idx >> 10) & (Kk - 1);
    int b = idx >> 13;
    float denom = g_S[b * Kk + k] + c_EPS;
    out[idx] = g_attn[((size_t)b * Nn + n) * Kk + k] / denom;
}

// ---------------- launcher ---------------------------------------------------
extern "C" void kernel_launch(void* const* d_in, const int* in_sizes, int n_in,
                              void* d_out, int out_size) {
    const float* embeddings = (const float*)d_in[0];
    const float* noise_init = (const float*)d_in[1];
    const float* noise_final= (const float*)d_in[2];
    const float* slots_mu   = (const float*)d_in[3];
    const float* slots_ls   = (const float*)d_in[4];
    const float* mixing     = (const float*)d_in[5];
    const float* Wk = (const float*)d_in[6];
    const float* bk = (const float*)d_in[7];
    const float* Wq = (const float*)d_in[8];
    const float* bq = (const float*)d_in[9];
    const float* Wv = (const float*)d_in[10];
    const float* bv = (const float*)d_in[11];
    const float* lng = (const float*)d_in[12];
    const float* lnb = (const float*)d_in[13];
    float* out = (float*)d_out;

    ln_split<<<Mtot, 128>>>(embeddings, lng, lnb);
    wt_split<<<dim3(32, 16), dim3(32, 8)>>>(Wk, Wv);
    init_slots_queries<<<Bb * Kk, 128>>>(noise_init, slots_mu, slots_ls, mixing, Wq, bq);
    mma_kv<<<dim3(Ntot / 128, Mtot / 128), 256>>>(bk, bv);

    for (int it = 0; it < NITER; it++) {
        prep_iter<<<Bb * Kk, 128>>>();
        gll_attn<<<dim3(Bb, NROWCHUNK), 256>>>();
        mu_partial<<<dim3(Bb, 4, NCHUNK), 128>>>();
        reduce_update<<<Bb * Kk, 128>>>();
    }

    final_slots<<<(Bb * Kk * Dd) / 256, 256>>>(noise_final, out);
    attn_out<<<(Bb * Kk * Nn) / 256, 256>>>(out + Bb * Kk * Dd);
}